// round 16
// baseline (speedup 1.0000x reference)
#include <cuda_runtime.h>
#include <cuda_fp16.h>

#define B_  2
#define T_  512
#define E_  768
#define H_  12
#define HD_ 64

__device__ __half g_xh[B_ * T_ * E_];
__device__ __half g_wh[3 * E_ * E_];
__device__ __half g_qh[B_ * T_ * E_];
__device__ __half g_kh[B_ * T_ * E_];
__device__ __half g_vt[B_ * E_ * T_];
__device__ __half g_kph[B_ * H_ * T_ * 8 * HD_];

// slot of k within a 16-chunk for fp16 mma fragments
__device__ __forceinline__ int s16(int k) {
    return 4 * ((k >> 1) & 3) + 2 * ((k >> 3) & 1) + (k & 1);
}
// position of k within a 64-block: chunk-pairs of 32, thread-slot interleaved
__device__ __forceinline__ int hperm64(int w) {
    int p = w >> 5, c1 = (w >> 4) & 1, k0 = w & 15;
    return p * 32 + ((k0 >> 1) & 3) * 8 + c1 * 4 + ((k0 >> 3) & 1) * 2 + (k0 & 1);
}

__device__ __forceinline__ void mma_f16(
    float& d0, float& d1, float& d2, float& d3,
    unsigned a0, unsigned a1, unsigned a2, unsigned a3,
    unsigned b0, unsigned b1)
{
    asm volatile(
        "mma.sync.aligned.m16n8k16.row.col.f32.f16.f16.f32 "
        "{%0,%1,%2,%3}, {%4,%5,%6,%7}, {%8,%9}, {%0,%1,%2,%3};"
        : "+f"(d0), "+f"(d1), "+f"(d2), "+f"(d3)
        : "r"(a0), "r"(a1), "r"(a2), "r"(a3), "r"(b0), "r"(b1));
}

__device__ __forceinline__ unsigned smem_u32(const void* p) {
    return (unsigned)__cvta_generic_to_shared(p);
}
__device__ __forceinline__ void cp_async16(unsigned s, const void* g) {
    asm volatile("cp.async.cg.shared.global [%0], [%1], 16;" :: "r"(s), "l"(g));
}
__device__ __forceinline__ void cp_commit()   { asm volatile("cp.async.commit_group;"); }
__device__ __forceinline__ void cp_wait1()    { asm volatile("cp.async.wait_group 1;"); }
__device__ __forceinline__ void cp_wait_all() { asm volatile("cp.async.wait_group 0;"); }

// ---------------------------------------------------------------------------
// Kernel 0: fp32 -> fp16 with k-permutation, smem-coalesced stores.
// ---------------------------------------------------------------------------
__global__ __launch_bounds__(192) void prep(
    const float* __restrict__ x,  const float* __restrict__ wq,
    const float* __restrict__ wk, const float* __restrict__ wv)
{
    __shared__ __align__(16) __half Hs[768];
    const int z = blockIdx.y;
    const float* src; __half* dst; int nrows;
    if (z == 0)      { src = x;  dst = g_xh;               nrows = B_ * T_; }
    else if (z == 1) { src = wq; dst = g_wh;               nrows = E_; }
    else if (z == 2) { src = wk; dst = g_wh + E_ * E_;     nrows = E_; }
    else             { src = wv; dst = g_wh + 2 * E_ * E_; nrows = E_; }
    const int row = blockIdx.x;
    if (row >= nrows) return;
    const int tid = threadIdx.x;
    const int c0 = tid * 4;
    float4 v = *(const float4*)&src[(size_t)row * E_ + c0];
    const int blk = (c0 >> 6) * 64, w = c0 & 63;
    *(__half2*)&Hs[blk + hperm64(w)]     = __floats2half2_rn(v.x, v.y);
    *(__half2*)&Hs[blk + hperm64(w + 2)] = __floats2half2_rn(v.z, v.w);
    __syncthreads();
    if (tid < 96)
        *(uint4*)&dst[(size_t)row * E_ + tid * 8] = *(const uint4*)&Hs[tid * 8];
}

// ---------------------------------------------------------------------------
// Kernel 1: QKV projection, fp16 mma, 3-buffer depth-2 cp.async pipeline.
// ---------------------------------------------------------------------------
__global__ __launch_bounds__(256) void qkv_mma(
    const float* __restrict__ bq, const float* __restrict__ bk,
    const float* __restrict__ bv)
{
    __shared__ __align__(16) __half sh[12288];   // X 3x2048 | W 3x2048
    const int z = blockIdx.z;
    const __half* Wg = g_wh + (size_t)z * E_ * E_;
    const float* bias = (z == 0) ? bq : (z == 1) ? bk : bv;

    const int tid  = threadIdx.x;
    const int lane = tid & 31;
    const int warp = tid >> 5;
    const int gid  = lane >> 2;
    const int tig  = lane & 3;
    const int mw   = warp & 3;
    const int nw   = warp >> 2;
    const int m0 = blockIdx.y * 64;
    const int n0 = blockIdx.x * 64;

    const unsigned sh_s = smem_u32(sh);
    const int srow = tid & 63;
    const int sslot = tid >> 6;

    auto stage = [&](int it) {
        const int buf = it % 3;
        const int k0 = it * 32;
        const int swz = (sslot ^ (srow & 3)) * 16;
        cp_async16(sh_s + (unsigned)((buf * 2048 + srow * 32) * 2 + swz),
                   g_xh + (size_t)(m0 + srow) * E_ + k0 + sslot * 8);
        cp_async16(sh_s + (unsigned)((6144 + buf * 2048 + srow * 32) * 2 + swz),
                   Wg + (size_t)(n0 + srow) * E_ + k0 + sslot * 8);
        cp_commit();
    };

    float acc[4][4];
    #pragma unroll
    for (int nb = 0; nb < 4; nb++)
        #pragma unroll
        for (int i = 0; i < 4; i++) acc[nb][i] = 0.f;

    stage(0);
    stage(1);

    for (int it = 0; it < 24; it++) {
        if (it == 23) cp_wait_all(); else cp_wait1();  // stage(it) complete
        __syncthreads();       // all warps done reading buf (it-1)%3
        if (it + 2 < 24) stage(it + 2);   // writes buf (it+2)%3 == (it-1)%3

        const __half* Xb = sh + (it % 3) * 2048;
        const __half* Wb = sh + 6144 + (it % 3) * 2048;
        const int m = mw * 16 + gid, m8 = m + 8;
        uint4 xa = *(const uint4*)(Xb + m * 32 + ((tig ^ (m & 3)) * 8));
        uint4 xb = *(const uint4*)(Xb + m8 * 32 + ((tig ^ (m8 & 3)) * 8));
        #pragma unroll
        for (int nb = 0; nb < 4; nb++) {
            const int n = nw * 32 + nb * 8 + gid;
            uint4 wb = *(const uint4*)(Wb + n * 32 + ((tig ^ (n & 3)) * 8));
            mma_f16(acc[nb][0], acc[nb][1], acc[nb][2], acc[nb][3],
                    xa.x, xb.x, xa.y, xb.y, wb.x, wb.y);
            mma_f16(acc[nb][0], acc[nb][1], acc[nb][2], acc[nb][3],
                    xa.z, xb.z, xa.w, xb.w, wb.z, wb.w);
        }
    }
    __syncthreads();           // loop done before epilogue reuses sh

    // epilogue via smem tile (stride 80 halves) for coalesced stores
    __half* Hs = sh;
    if (z < 2) {
        #pragma unroll
        for (int nb = 0; nb < 4; nb++) {
            const int cl = nw * 32 + nb * 8 + 2 * tig;
            const float bz0 = bias[n0 + cl], bz1 = bias[n0 + cl + 1];
            const int ml = mw * 16 + gid;
            const int pos = hperm64(cl);
            *(__half2*)&Hs[ml * 80 + pos] =
                __floats2half2_rn(acc[nb][0] + bz0, acc[nb][1] + bz1);
            *(__half2*)&Hs[(ml + 8) * 80 + pos] =
                __floats2half2_rn(acc[nb][2] + bz0, acc[nb][3] + bz1);
        }
        __syncthreads();
        __half* o = z ? g_kh : g_qh;
        #pragma unroll
        for (int i = 0; i < 2; i++) {
            int idx = tid + i * 256;
            int r = idx >> 3, cu = (idx & 7) * 8;
            *(uint4*)&o[(size_t)(m0 + r) * E_ + n0 + cu] = *(const uint4*)&Hs[r * 80 + cu];
        }
    } else {
        #pragma unroll
        for (int nb = 0; nb < 4; nb++) {
            const int cl = nw * 32 + nb * 8 + 2 * tig;
            const float bz0 = bias[n0 + cl], bz1 = bias[n0 + cl + 1];
            const int t  = mw * 16 + gid;
            const int tp  = (t & ~15) | s16(t & 15);
            const int tp8 = ((t + 8) & ~15) | s16((t + 8) & 15);
            Hs[cl * 80 + tp]        = __float2half_rn(acc[nb][0] + bz0);
            Hs[(cl + 1) * 80 + tp]  = __float2half_rn(acc[nb][1] + bz1);
            Hs[cl * 80 + tp8]       = __float2half_rn(acc[nb][2] + bz0);
            Hs[(cl + 1) * 80 + tp8] = __float2half_rn(acc[nb][3] + bz1);
        }
        __syncthreads();
        const int bb = m0 >> 9;
        const int t0g = m0 & 511;
        #pragma unroll
        for (int i = 0; i < 2; i++) {
            int idx = tid + i * 256;
            int r = idx >> 3, cu = (idx & 7) * 8;
            *(uint4*)&g_vt[((size_t)(bb * E_ + n0 + r)) * T_ + t0g + cu] =
                *(const uint4*)&Hs[r * 80 + cu];
        }
    }
}

// ---------------------------------------------------------------------------
// Kernel 1.5: K' fold, weights transposed in smem to [oq][kh][g] so the
// per-kh inner read is 3 broadcast LDS.128 (12 contiguous half2).
// grid (T, B), 256 threads (warp = oq, lane = i).
// ---------------------------------------------------------------------------
__global__ __launch_bounds__(256) void kprep(const float* __restrict__ w1)
{
    __shared__ __align__(16) __half Ksm[768];
    __shared__ __align__(16) __half2 w1t[1152];   // [oq][kh][g]
    const int b = blockIdx.y;
    const int t = blockIdx.x;
    const int tid = threadIdx.x;
    const float inv_scale = 0.03608439182435161f;

    if (tid < 96)
        *(uint4*)&Ksm[tid * 8] =
            *(const uint4*)&g_kh[(size_t)(b * T_ + t) * E_ + tid * 8];
    for (int idx = tid; idx < 1152; idx += 256) {
        const int oq = idx / 144;
        const int rem = idx - oq * 144;
        const int kh = rem / 12;
        const int g  = rem - kh * 12;
        float w = w1[(g * 8 + oq) * 12 + kh] * inv_scale;
        w1t[idx] = __float2half2_rn(w);
    }
    __syncthreads();

    const int oq = tid >> 5;      // warp id -> o (warp-constant)
    const int i  = tid & 31;      // lane -> half2 position within d-block
    __half2 kf[12];
    #pragma unroll
    for (int kh = 0; kh < 12; kh++)
        kf[kh] = *(const __half2*)&Ksm[kh * 64 + 2 * i];

    __half2 acc[12];
    #pragma unroll
    for (int g = 0; g < 12; g++) acc[g] = __float2half2_rn(0.f);

    const __half2* wbase = w1t + oq * 144;
    #pragma unroll
    for (int kh = 0; kh < 12; kh++) {
        const __half2 k2 = kf[kh];
        const uint4* wp = (const uint4*)(wbase + kh * 12);   // 3 x LDS.128 broadcast
        #pragma unroll
        for (int j = 0; j < 3; j++) {
            uint4 wv = wp[j];
            const __half2* w4 = (const __half2*)&wv;
            acc[j*4+0] = __hfma2(w4[0], k2, acc[j*4+0]);
            acc[j*4+1] = __hfma2(w4[1], k2, acc[j*4+1]);
            acc[j*4+2] = __hfma2(w4[2], k2, acc[j*4+2]);
            acc[j*4+3] = __hfma2(w4[3], k2, acc[j*4+3]);
        }
    }

    __half2* outp = (__half2*)g_kph;
    const size_t base = ((size_t)b * H_ * T_ + t) * 8;
    #pragma unroll
    for (int g = 0; g < 12; g++)
        outp[(base + (size_t)g * T_ * 8 + oq) * 32 + i] = acc[g];
}

// ---------------------------------------------------------------------------
// Kernel 2: fused hidden(fp16 mma) -> MLP tail (reduce-scatter) -> ctx(mma).
// TK=32, round-7 ordering (known-good).
// ---------------------------------------------------------------------------
#define TK 32
#define LT 32
#define KS_HALVES 16384
#define VS_HALVES 4096
#define WS_HALVES 1536

__global__ __launch_bounds__(256, 3) void attn_fused(
    const float* __restrict__ b1, const float* __restrict__ w2,
    const float* __restrict__ b2, const float* __restrict__ w3,
    const float* __restrict__ b3, const float* __restrict__ w4,
    const float* __restrict__ b4, float* __restrict__ out)
{
    __shared__ __align__(16) __half Ks[KS_HALVES];
    __shared__ __align__(16) __half VsT[VS_HALVES];
    __shared__ __align__(16) __half Ws[WS_HALVES];

    const int b  = blockIdx.z;
    const int g  = blockIdx.y;
    const int l0 = blockIdx.x * LT;
    const int tid  = threadIdx.x;
    const int lane = tid & 31;
    const int warp = tid >> 5;
    const int gid  = lane >> 2;
    const int tig  = lane & 3;
    const int lb   = warp >> 2;
    const int wn   = warp & 3;

    const float b1lo = __ldg(&b1[g * 8 + 2 * tig]);
    const float b1hi = __ldg(&b1[g * 8 + 2 * tig + 1]);
    const float w2lo = __ldg(&w2[g * 8 + 2 * tig]);
    const float w2hi = __ldg(&w2[g * 8 + 2 * tig + 1]);
    const float b2r = __ldg(&b2[g]), b4r = __ldg(&b4[g]);
    float w3r[4], b3r[4], w4r[4];
    #pragma unroll
    for (int j = 0; j < 4; j++) {
        w3r[j] = __ldg(&w3[g * 4 + j]);
        b3r[j] = __ldg(&b3[g * 4 + j]);
        w4r[j] = __ldg(&w4[g * 4 + j]);
    }

    const int row0 = b * T_ + l0 + lb * 16 + gid;

    uint4 qa[2], qb[2];
    {
        const __half* q0 = g_qh + (size_t)row0 * E_ + g * 64;
        const __half* q1 = g_qh + (size_t)(row0 + 8) * E_ + g * 64;
        #pragma unroll
        for (int p = 0; p < 2; p++) {
            qa[p] = *(const uint4*)(q0 + p * 32 + tig * 8);
            qb[p] = *(const uint4*)(q1 + p * 32 + tig * 8);
        }
    }

    const __half* Kg = g_kph + (size_t)(b * H_ + g) * (T_ * 8 * HD_);
    const unsigned ks_s = smem_u32(Ks);
    const unsigned vs_s = smem_u32(VsT);

    auto stage = [&](int tile) {
        const __half* kt = Kg + (size_t)tile * (TK * 8 * HD_);
        #pragma unroll
        for (int i = 0; i < 8; i++) {
            int idx = tid + i * 256;
            int r = idx >> 3, c = idx & 7;
            int cs = c ^ (4 * (r & 1));
            cp_async16(ks_s + (unsigned)(r * 128 + cs * 16), kt + (size_t)idx * 8);
        }
        {
            int kc = tid >> 7, r = (tid >> 1) & 63, s = tid & 1;
            cp_async16(vs_s + (unsigned)(((tile & 1) * 2048 + kc * 1024 + r * 16 + s * 8) * 2),
                       g_vt + ((size_t)(b * E_ + g * 64 + r)) * T_ + tile * TK + kc * 16 + s * 8);
        }
        cp_commit();
    };

    stage(0);
    cp_wait_all();
    __syncthreads();

    float cacc[2][4] = {};
    const int kboff = tig * 8 + (gid & 1) * 32;
    const int st = s16(wn * 4 + tig);
    const bool lo1 = (tig & 1) == 0;
    const bool lo2 = (tig & 2) == 0;
    __half* ws_w0 = Ws + (lb * 16 + gid) * 48 + st;
    __half* ws_w1 = ws_w0 + 8 * 48;

    for (int ti = 0; ti < T_ / TK; ti++) {
        const bool more = (ti + 1) < (T_ / TK);

        #pragma unroll
        for (int ph = 0; ph < 2; ph++) {
            // ---- hidden = b1 + Q.K' ----
            float d[4][4];
            #pragma unroll
            for (int nb = 0; nb < 4; nb++) {
                d[nb][0] = b1lo; d[nb][1] = b1hi; d[nb][2] = b1lo; d[nb][3] = b1hi;
            }
            #pragma unroll
            for (int nb = 0; nb < 4; nb++) {
                const __half* kr = Ks + (((ph * 16 + wn * 4 + nb) * 8) + gid) * 64;
                uint4 kb0 = *(const uint4*)(kr + kboff);
                uint4 kb1 = *(const uint4*)(kr + (kboff ^ 32));
                mma_f16(d[nb][0], d[nb][1], d[nb][2], d[nb][3],
                        qa[0].x, qb[0].x, qa[0].y, qb[0].y, kb0.x, kb0.y);
                mma_f16(d[nb][0], d[nb][1], d[nb][2], d[nb][3],
                        qa[0].z, qb[0].z, qa[0].w, qb[0].w, kb0.z, kb0.w);
                mma_f16(d[nb][0], d[nb][1], d[nb][2], d[nb][3],
                        qa[1].x, qb[1].x, qa[1].y, qb[1].y, kb1.x, kb1.y);
                mma_f16(d[nb][0], d[nb][1], d[nb][2], d[nb][3],
                        qa[1].z, qb[1].z, qa[1].w, qb[1].w, kb1.z, kb1.w);
            }

            // ---- u = w2 . relu(h) partials ----
            float u0[4], u1[4];
            #pragma unroll
            for (int nb = 0; nb < 4; nb++) {
                u0[nb] = fmaf(w2lo, fmaxf(d[nb][0], 0.f), w2hi * fmaxf(d[nb][1], 0.f));
                u1[nb] = fmaf(w2lo, fmaxf(d[nb][2], 0.f), w2hi * fmaxf(d[nb][3], 0.f));
            }

            // ---- quad reduce-scatter ----
            float a0, a1;
            {
                float k0 = lo1 ? u0[0] : u0[1], s0 = lo1 ? u0[1] : u0[0];
                k0 += __shfl_xor_sync(0xffffffffu, s0, 1);
                float k1 = lo1 ? u0[2] : u0[3], s1 = lo1 ? u0[3] : u0[2];
                k1 += __shfl_xor_sync(0xffffffffu, s1, 1);
                float kk = lo2 ? k0 : k1, ss = lo2 ? k1 : k0;
                a0 = kk + __shfl_xor_sync(0xffffffffu, ss, 2);
            }
            {
                float k0 = lo1 ? u1[0] : u1[1], s0 = lo1 ? u1[1] : u1[0];
                k0 += __shfl_xor_sync(0xffffffffu, s0, 1);
                float k1 = lo1 ? u1[2] : u1[3], s1 = lo1 ? u1[3] : u1[2];
                k1 += __shfl_xor_sync(0xffffffffu, s1, 1);
                float kk = lo2 ? k0 : k1, ss = lo2 ? k1 : k0;
                a1 = kk + __shfl_xor_sync(0xffffffffu, ss, 2);
            }

            // ---- tail once per thread ----
            float a20 = a0 + b2r, a21 = a1 + b2r;
            float wv0 = b4r, wv1 = b4r;
            #pragma unroll
            for (int j = 0; j < 4; j++) {
                wv0 = fmaf(w4r[j], fmaxf(fmaf(w3r[j], a20, b3r[j]), 0.f), wv0);
                wv1 = fmaf(w4r[j], fmaxf(fmaf(w3r[j], a21, b3r[j]), 0.f), wv1);
            }
            ws_w0[ph * 16] = __float2half_rn(wv0);
            ws_w1[ph * 16] = __float2half_rn(wv1);
        }
        __syncthreads();

        if (more) stage(ti + 1);

        // ---- ctx: cacc += Ws[32,32] @ V[32,64] ----
        const __half* Vb = VsT + (ti & 1) * 2048;
        #pragma unroll
        for (int kc = 0; kc < 2; kc++) {
            uint2 wa  = *(const uint2*)&Ws[(lb * 16 + gid) * 48 + kc * 16 + tig * 4];
            uint2 wbv = *(const uint2*)&Ws[(lb * 16 + gid + 8) * 48 + kc * 16 + tig * 4];
            #pragma unroll
            for (int nd = 0; nd < 2; nd++) {
                const int dr = wn * 16 + nd * 8 + gid;
                uint2 vb = *(const uint2*)&Vb[kc * 1024 + dr * 16 + tig * 4];
                mma_f16(cacc[nd][0], cacc[nd][1], cacc[nd][2], cacc[nd][3],
                        wa.x, wbv.x, wa.y, wbv.y, vb.x, vb.y);
            }
        }

        if (more) {
            cp_wait_all();
            __syncthreads();
        }
    }

    #pragma unroll
    for (int nd = 0; nd < 2; nd++) {
        const int col = g * 64 + wn * 16 + nd * 8 + 2 * tig;
        *(float2*)&out[(size_t)row0 * E_ + col] =
            make_float2(cacc[nd][0], cacc[nd][1]);
        *(float2*)&out[(size_t)(row0 + 8) * E_ + col] =
            make_float2(cacc[nd][2], cacc[nd][3]);
    }
}

// ---------------------------------------------------------------------------
extern "C" void kernel_launch(void* const* d_in, const int* in_sizes, int n_in,
                              void* d_out, int out_size)
{
    const float* x  = (const float*)d_in[0];
    const float* wq = (const float*)d_in[1];
    const float* bq = (const float*)d_in[2];
    const float* wk = (const float*)d_in[3];
    const float* bk = (const float*)d_in[4];
    const float* wv = (const float*)d_in[5];
    const float* bv = (const float*)d_in[6];
    const float* w1 = (const float*)d_in[7];
    const float* b1 = (const float*)d_in[8];
    const float* w2 = (const float*)d_in[9];
    const float* b2 = (const float*)d_in[10];
    const float* w3 = (const float*)d_in[11];
    const float* b3 = (const float*)d_in[12];
    const float* w4 = (const float*)d_in[13];
    const float* b4 = (const float*)d_in[14];
    float* out = (float*)d_out;

    dim3 pgrid(B_ * T_, 4);
    prep<<<pgrid, 192>>>(x, wq, wk, wv);

    dim3 ggrid(E_ / 64, (B_ * T_) / 64, 3);
    qkv_mma<<<ggrid, 256>>>(bq, bk, bv);

    dim3 kgrid(T_, B_);
    kprep<<<kgrid, 256>>>(w1);

    dim3 agrid(T_ / LT, H_, B_);
    attn_fused<<<agrid, 256>>>(b1, w2, b2, w3, b3, w4, b4, out);
}

// round 17
// speedup vs baseline: 1.0052x; 1.0052x over previous
#include <cuda_runtime.h>
#include <cuda_fp16.h>

#define B_  2
#define T_  512
#define E_  768
#define H_  12
#define HD_ 64

__device__ __half g_xh[B_ * T_ * E_];
__device__ __half g_wh[3 * E_ * E_];
__device__ __half g_qh[B_ * T_ * E_];
__device__ __half g_kh[B_ * T_ * E_];
__device__ __half g_vt[B_ * E_ * T_];
__device__ __half g_kph[B_ * H_ * T_ * 8 * HD_];

// slot of k within a 16-chunk for fp16 mma fragments
__device__ __forceinline__ int s16(int k) {
    return 4 * ((k >> 1) & 3) + 2 * ((k >> 3) & 1) + (k & 1);
}
// position of k within a 64-block: chunk-pairs of 32, thread-slot interleaved
__device__ __forceinline__ int hperm64(int w) {
    int p = w >> 5, c1 = (w >> 4) & 1, k0 = w & 15;
    return p * 32 + ((k0 >> 1) & 3) * 8 + c1 * 4 + ((k0 >> 3) & 1) * 2 + (k0 & 1);
}

__device__ __forceinline__ void mma_f16(
    float& d0, float& d1, float& d2, float& d3,
    unsigned a0, unsigned a1, unsigned a2, unsigned a3,
    unsigned b0, unsigned b1)
{
    asm volatile(
        "mma.sync.aligned.m16n8k16.row.col.f32.f16.f16.f32 "
        "{%0,%1,%2,%3}, {%4,%5,%6,%7}, {%8,%9}, {%0,%1,%2,%3};"
        : "+f"(d0), "+f"(d1), "+f"(d2), "+f"(d3)
        : "r"(a0), "r"(a1), "r"(a2), "r"(a3), "r"(b0), "r"(b1));
}

// fp16-accumulator variant: C/D are two .f16x2 regs
__device__ __forceinline__ void mma_f16acc(
    unsigned& c0, unsigned& c1,
    unsigned a0, unsigned a1, unsigned a2, unsigned a3,
    unsigned b0, unsigned b1)
{
    asm volatile(
        "mma.sync.aligned.m16n8k16.row.col.f16.f16.f16.f16 "
        "{%0,%1}, {%2,%3,%4,%5}, {%6,%7}, {%0,%1};"
        : "+r"(c0), "+r"(c1)
        : "r"(a0), "r"(a1), "r"(a2), "r"(a3), "r"(b0), "r"(b1));
}

__device__ __forceinline__ unsigned smem_u32(const void* p) {
    return (unsigned)__cvta_generic_to_shared(p);
}
__device__ __forceinline__ void cp_async16(unsigned s, const void* g) {
    asm volatile("cp.async.cg.shared.global [%0], [%1], 16;" :: "r"(s), "l"(g));
}
__device__ __forceinline__ void cp_commit()   { asm volatile("cp.async.commit_group;"); }
__device__ __forceinline__ void cp_wait1()    { asm volatile("cp.async.wait_group 1;"); }
__device__ __forceinline__ void cp_wait_all() { asm volatile("cp.async.wait_group 0;"); }

__device__ __forceinline__ unsigned h2u(__half2 h) {
    return *reinterpret_cast<unsigned*>(&h);
}
__device__ __forceinline__ __half2 u2h(unsigned u) {
    return *reinterpret_cast<__half2*>(&u);
}

// ---------------------------------------------------------------------------
// Kernel 0: fp32 -> fp16 with k-permutation, smem-coalesced stores.
// ---------------------------------------------------------------------------
__global__ __launch_bounds__(192) void prep(
    const float* __restrict__ x,  const float* __restrict__ wq,
    const float* __restrict__ wk, const float* __restrict__ wv)
{
    __shared__ __align__(16) __half Hs[768];
    const int z = blockIdx.y;
    const float* src; __half* dst; int nrows;
    if (z == 0)      { src = x;  dst = g_xh;               nrows = B_ * T_; }
    else if (z == 1) { src = wq; dst = g_wh;               nrows = E_; }
    else if (z == 2) { src = wk; dst = g_wh + E_ * E_;     nrows = E_; }
    else             { src = wv; dst = g_wh + 2 * E_ * E_; nrows = E_; }
    const int row = blockIdx.x;
    if (row >= nrows) return;
    const int tid = threadIdx.x;
    const int c0 = tid * 4;
    float4 v = *(const float4*)&src[(size_t)row * E_ + c0];
    const int blk = (c0 >> 6) * 64, w = c0 & 63;
    *(__half2*)&Hs[blk + hperm64(w)]     = __floats2half2_rn(v.x, v.y);
    *(__half2*)&Hs[blk + hperm64(w + 2)] = __floats2half2_rn(v.z, v.w);
    __syncthreads();
    if (tid < 96)
        *(uint4*)&dst[(size_t)row * E_ + tid * 8] = *(const uint4*)&Hs[tid * 8];
}

// ---------------------------------------------------------------------------
// Kernel 1: QKV projection, fp16 mma, 3-buffer depth-2 cp.async pipeline.
// ---------------------------------------------------------------------------
__global__ __launch_bounds__(256) void qkv_mma(
    const float* __restrict__ bq, const float* __restrict__ bk,
    const float* __restrict__ bv)
{
    __shared__ __align__(16) __half sh[12288];   // X 3x2048 | W 3x2048
    const int z = blockIdx.z;
    const __half* Wg = g_wh + (size_t)z * E_ * E_;
    const float* bias = (z == 0) ? bq : (z == 1) ? bk : bv;

    const int tid  = threadIdx.x;
    const int lane = tid & 31;
    const int warp = tid >> 5;
    const int gid  = lane >> 2;
    const int tig  = lane & 3;
    const int mw   = warp & 3;
    const int nw   = warp >> 2;
    const int m0 = blockIdx.y * 64;
    const int n0 = blockIdx.x * 64;

    const unsigned sh_s = smem_u32(sh);
    const int srow = tid & 63;
    const int sslot = tid >> 6;

    auto stage = [&](int it) {
        const int buf = it % 3;
        const int k0 = it * 32;
        const int swz = (sslot ^ (srow & 3)) * 16;
        cp_async16(sh_s + (unsigned)((buf * 2048 + srow * 32) * 2 + swz),
                   g_xh + (size_t)(m0 + srow) * E_ + k0 + sslot * 8);
        cp_async16(sh_s + (unsigned)((6144 + buf * 2048 + srow * 32) * 2 + swz),
                   Wg + (size_t)(n0 + srow) * E_ + k0 + sslot * 8);
        cp_commit();
    };

    float acc[4][4];
    #pragma unroll
    for (int nb = 0; nb < 4; nb++)
        #pragma unroll
        for (int i = 0; i < 4; i++) acc[nb][i] = 0.f;

    stage(0);
    stage(1);

    for (int it = 0; it < 24; it++) {
        if (it == 23) cp_wait_all(); else cp_wait1();  // stage(it) complete
        __syncthreads();       // all warps done reading buf (it-1)%3
        if (it + 2 < 24) stage(it + 2);   // writes buf (it+2)%3 == (it-1)%3

        const __half* Xb = sh + (it % 3) * 2048;
        const __half* Wb = sh + 6144 + (it % 3) * 2048;
        const int m = mw * 16 + gid, m8 = m + 8;
        uint4 xa = *(const uint4*)(Xb + m * 32 + ((tig ^ (m & 3)) * 8));
        uint4 xb = *(const uint4*)(Xb + m8 * 32 + ((tig ^ (m8 & 3)) * 8));
        #pragma unroll
        for (int nb = 0; nb < 4; nb++) {
            const int n = nw * 32 + nb * 8 + gid;
            uint4 wb = *(const uint4*)(Wb + n * 32 + ((tig ^ (n & 3)) * 8));
            mma_f16(acc[nb][0], acc[nb][1], acc[nb][2], acc[nb][3],
                    xa.x, xb.x, xa.y, xb.y, wb.x, wb.y);
            mma_f16(acc[nb][0], acc[nb][1], acc[nb][2], acc[nb][3],
                    xa.z, xb.z, xa.w, xb.w, wb.z, wb.w);
        }
    }
    __syncthreads();           // loop done before epilogue reuses sh

    // epilogue via smem tile (stride 80 halves) for coalesced stores
    __half* Hs = sh;
    if (z < 2) {
        #pragma unroll
        for (int nb = 0; nb < 4; nb++) {
            const int cl = nw * 32 + nb * 8 + 2 * tig;
            const float bz0 = bias[n0 + cl], bz1 = bias[n0 + cl + 1];
            const int ml = mw * 16 + gid;
            const int pos = hperm64(cl);
            *(__half2*)&Hs[ml * 80 + pos] =
                __floats2half2_rn(acc[nb][0] + bz0, acc[nb][1] + bz1);
            *(__half2*)&Hs[(ml + 8) * 80 + pos] =
                __floats2half2_rn(acc[nb][2] + bz0, acc[nb][3] + bz1);
        }
        __syncthreads();
        __half* o = z ? g_kh : g_qh;
        #pragma unroll
        for (int i = 0; i < 2; i++) {
            int idx = tid + i * 256;
            int r = idx >> 3, cu = (idx & 7) * 8;
            *(uint4*)&o[(size_t)(m0 + r) * E_ + n0 + cu] = *(const uint4*)&Hs[r * 80 + cu];
        }
    } else {
        #pragma unroll
        for (int nb = 0; nb < 4; nb++) {
            const int cl = nw * 32 + nb * 8 + 2 * tig;
            const float bz0 = bias[n0 + cl], bz1 = bias[n0 + cl + 1];
            const int t  = mw * 16 + gid;
            const int tp  = (t & ~15) | s16(t & 15);
            const int tp8 = ((t + 8) & ~15) | s16((t + 8) & 15);
            Hs[cl * 80 + tp]        = __float2half_rn(acc[nb][0] + bz0);
            Hs[(cl + 1) * 80 + tp]  = __float2half_rn(acc[nb][1] + bz1);
            Hs[cl * 80 + tp8]       = __float2half_rn(acc[nb][2] + bz0);
            Hs[(cl + 1) * 80 + tp8] = __float2half_rn(acc[nb][3] + bz1);
        }
        __syncthreads();
        const int bb = m0 >> 9;
        const int t0g = m0 & 511;
        #pragma unroll
        for (int i = 0; i < 2; i++) {
            int idx = tid + i * 256;
            int r = idx >> 3, cu = (idx & 7) * 8;
            *(uint4*)&g_vt[((size_t)(bb * E_ + n0 + r)) * T_ + t0g + cu] =
                *(const uint4*)&Hs[r * 80 + cu];
        }
    }
}

// ---------------------------------------------------------------------------
// Kernel 1.5: K' fold, weights transposed in smem to [oq][kh][g].
// ---------------------------------------------------------------------------
__global__ __launch_bounds__(256) void kprep(const float* __restrict__ w1)
{
    __shared__ __align__(16) __half Ksm[768];
    __shared__ __align__(16) __half2 w1t[1152];   // [oq][kh][g]
    const int b = blockIdx.y;
    const int t = blockIdx.x;
    const int tid = threadIdx.x;
    const float inv_scale = 0.03608439182435161f;

    if (tid < 96)
        *(uint4*)&Ksm[tid * 8] =
            *(const uint4*)&g_kh[(size_t)(b * T_ + t) * E_ + tid * 8];
    for (int idx = tid; idx < 1152; idx += 256) {
        const int oq = idx / 144;
        const int rem = idx - oq * 144;
        const int kh = rem / 12;
        const int g  = rem - kh * 12;
        float w = w1[(g * 8 + oq) * 12 + kh] * inv_scale;
        w1t[idx] = __float2half2_rn(w);
    }
    __syncthreads();

    const int oq = tid >> 5;
    const int i  = tid & 31;
    __half2 kf[12];
    #pragma unroll
    for (int kh = 0; kh < 12; kh++)
        kf[kh] = *(const __half2*)&Ksm[kh * 64 + 2 * i];

    __half2 acc[12];
    #pragma unroll
    for (int g = 0; g < 12; g++) acc[g] = __float2half2_rn(0.f);

    const __half2* wbase = w1t + oq * 144;
    #pragma unroll
    for (int kh = 0; kh < 12; kh++) {
        const __half2 k2 = kf[kh];
        const uint4* wp = (const uint4*)(wbase + kh * 12);
        #pragma unroll
        for (int j = 0; j < 3; j++) {
            uint4 wv = wp[j];
            const __half2* w4 = (const __half2*)&wv;
            acc[j*4+0] = __hfma2(w4[0], k2, acc[j*4+0]);
            acc[j*4+1] = __hfma2(w4[1], k2, acc[j*4+1]);
            acc[j*4+2] = __hfma2(w4[2], k2, acc[j*4+2]);
            acc[j*4+3] = __hfma2(w4[3], k2, acc[j*4+3]);
        }
    }

    __half2* outp = (__half2*)g_kph;
    const size_t base = ((size_t)b * H_ * T_ + t) * 8;
    #pragma unroll
    for (int g = 0; g < 12; g++)
        outp[(base + (size_t)g * T_ * 8 + oq) * 32 + i] = acc[g];
}

// ---------------------------------------------------------------------------
// Kernel 2: fused hidden(fp16-acc mma) -> half2 MLP tail -> ctx(fp32 mma).
// TK=32, round-7 ordering.
// ---------------------------------------------------------------------------
#define TK 32
#define LT 32
#define KS_HALVES 16384
#define VS_HALVES 4096
#define WS_HALVES 1536

__global__ __launch_bounds__(256, 3) void attn_fused(
    const float* __restrict__ b1, const float* __restrict__ w2,
    const float* __restrict__ b2, const float* __restrict__ w3,
    const float* __restrict__ b3, const float* __restrict__ w4,
    const float* __restrict__ b4, float* __restrict__ out)
{
    __shared__ __align__(16) __half Ks[KS_HALVES];
    __shared__ __align__(16) __half VsT[VS_HALVES];
    __shared__ __align__(16) __half Ws[WS_HALVES];

    const int b  = blockIdx.z;
    const int g  = blockIdx.y;
    const int l0 = blockIdx.x * LT;
    const int tid  = threadIdx.x;
    const int lane = tid & 31;
    const int warp = tid >> 5;
    const int gid  = lane >> 2;
    const int tig  = lane & 3;
    const int lb   = warp >> 2;
    const int wn   = warp & 3;

    // packed fp16 constants
    const unsigned b1p = h2u(__floats2half2_rn(__ldg(&b1[g * 8 + 2 * tig]),
                                               __ldg(&b1[g * 8 + 2 * tig + 1])));
    const __half2 w2h = __floats2half2_rn(__ldg(&w2[g * 8 + 2 * tig]),
                                          __ldg(&w2[g * 8 + 2 * tig + 1]));
    const __half2 b2h = __float2half2_rn(__ldg(&b2[g]));
    const __half2 b4h = __float2half2_rn(__ldg(&b4[g]));
    __half2 w3h[4], b3h[4], w4h[4];
    #pragma unroll
    for (int j = 0; j < 4; j++) {
        w3h[j] = __float2half2_rn(__ldg(&w3[g * 4 + j]));
        b3h[j] = __float2half2_rn(__ldg(&b3[g * 4 + j]));
        w4h[j] = __float2half2_rn(__ldg(&w4[g * 4 + j]));
    }
    const __half2 z2 = __float2half2_rn(0.f);

    const int row0 = b * T_ + l0 + lb * 16 + gid;

    uint4 qa[2], qb[2];
    {
        const __half* q0 = g_qh + (size_t)row0 * E_ + g * 64;
        const __half* q1 = g_qh + (size_t)(row0 + 8) * E_ + g * 64;
        #pragma unroll
        for (int p = 0; p < 2; p++) {
            qa[p] = *(const uint4*)(q0 + p * 32 + tig * 8);
            qb[p] = *(const uint4*)(q1 + p * 32 + tig * 8);
        }
    }

    const __half* Kg = g_kph + (size_t)(b * H_ + g) * (T_ * 8 * HD_);
    const unsigned ks_s = smem_u32(Ks);
    const unsigned vs_s = smem_u32(VsT);

    auto stage = [&](int tile) {
        const __half* kt = Kg + (size_t)tile * (TK * 8 * HD_);
        #pragma unroll
        for (int i = 0; i < 8; i++) {
            int idx = tid + i * 256;
            int r = idx >> 3, c = idx & 7;
            int cs = c ^ (4 * (r & 1));
            cp_async16(ks_s + (unsigned)(r * 128 + cs * 16), kt + (size_t)idx * 8);
        }
        {
            int kc = tid >> 7, r = (tid >> 1) & 63, s = tid & 1;
            cp_async16(vs_s + (unsigned)(((tile & 1) * 2048 + kc * 1024 + r * 16 + s * 8) * 2),
                       g_vt + ((size_t)(b * E_ + g * 64 + r)) * T_ + tile * TK + kc * 16 + s * 8);
        }
        cp_commit();
    };

    stage(0);
    cp_wait_all();
    __syncthreads();

    float cacc[2][4] = {};
    const int kboff = tig * 8 + (gid & 1) * 32;
    const int st = s16(wn * 4 + tig);
    const bool lo1 = (tig & 1) == 0;
    const bool lo2 = (tig & 2) == 0;
    __half* ws_w0 = Ws + (lb * 16 + gid) * 48 + st;
    __half* ws_w1 = ws_w0 + 8 * 48;

    for (int ti = 0; ti < T_ / TK; ti++) {
        const bool more = (ti + 1) < (T_ / TK);

        #pragma unroll
        for (int ph = 0; ph < 2; ph++) {
            // ---- hidden = b1 + Q.K'  (fp16 accumulators) ----
            unsigned dh[4][2];
            #pragma unroll
            for (int nb = 0; nb < 4; nb++) { dh[nb][0] = b1p; dh[nb][1] = b1p; }
            #pragma unroll
            for (int nb = 0; nb < 4; nb++) {
                const __half* kr = Ks + (((ph * 16 + wn * 4 + nb) * 8) + gid) * 64;
                uint4 kb0 = *(const uint4*)(kr + kboff);
                uint4 kb1 = *(const uint4*)(kr + (kboff ^ 32));
                mma_f16acc(dh[nb][0], dh[nb][1],
                           qa[0].x, qb[0].x, qa[0].y, qb[0].y, kb0.x, kb0.y);
                mma_f16acc(dh[nb][0], dh[nb][1],
                           qa[0].z, qb[0].z, qa[0].w, qb[0].w, kb0.z, kb0.w);
                mma_f16acc(dh[nb][0], dh[nb][1],
                           qa[1].x, qb[1].x, qa[1].y, qb[1].y, kb1.x, kb1.y);
                mma_f16acc(dh[nb][0], dh[nb][1],
                           qa[1].z, qb[1].z, qa[1].w, qb[1].w, kb1.z, kb1.w);
            }

            // ---- u-partials: half2 relu*w2, horizontal add, pack 2 l-rows ----
            __half2 up[4];
            #pragma unroll
            for (int nb = 0; nb < 4; nb++) {
                __half2 r0 = __hmul2(__hmax2(u2h(dh[nb][0]), z2), w2h);
                __half2 r1 = __hmul2(__hmax2(u2h(dh[nb][1]), z2), w2h);
                up[nb] = __halves2half2(__hadd(__low2half(r0), __high2half(r0)),
                                        __hadd(__low2half(r1), __high2half(r1)));
            }

            // ---- quad reduce-scatter on packed half2 (both l-rows at once) ----
            __half2 a;
            {
                __half2 k0 = lo1 ? up[0] : up[1], s0 = lo1 ? up[1] : up[0];
                k0 = __hadd2(k0, __shfl_xor_sync(0xffffffffu, s0, 1));
                __half2 k1 = lo1 ? up[2] : up[3], s1 = lo1 ? up[3] : up[2];
                k1 = __hadd2(k1, __shfl_xor_sync(0xffffffffu, s1, 1));
                __half2 kk = lo2 ? k0 : k1, ss = lo2 ? k1 : k0;
                a = __hadd2(kk, __shfl_xor_sync(0xffffffffu, ss, 2));
            }

            // ---- tail in half2, both l-rows simultaneously ----
            __half2 a2 = __hadd2(a, b2h);
            __half2 wv = b4h;
            #pragma unroll
            for (int j = 0; j < 4; j++)
                wv = __hfma2(w4h[j], __hmax2(__hfma2(w3h[j], a2, b3h[j]), z2), wv);

            ws_w0[ph * 16] = __low2half(wv);
            ws_w1[ph * 16] = __high2half(wv);
        }
        __syncthreads();

        if (more) stage(ti + 1);

        // ---- ctx: cacc += Ws[32,32] @ V[32,64]  (fp32 accumulators) ----
        const __half* Vb = VsT + (ti & 1) * 2048;
        #pragma unroll
        for (int kc = 0; kc < 2; kc++) {
            uint2 wa  = *(const uint2*)&Ws[(lb * 16 + gid) * 48 + kc * 16 + tig * 4];
            uint2 wbv = *(const uint2*)&Ws[(lb * 16 + gid + 8) * 48 + kc * 16 + tig * 4];
            #pragma unroll
            for (int nd = 0; nd < 2; nd++) {
                const int dr = wn * 16 + nd * 8 + gid;
                uint2 vb = *(const uint2*)&Vb[kc * 1024 + dr * 16 + tig * 4];
                mma_f16(cacc[nd][0], cacc[nd][1], cacc[nd][2], cacc[nd][3],
                        wa.x, wbv.x, wa.y, wbv.y, vb.x, vb.y);
            }
        }

        if (more) {
            cp_wait_all();
            __syncthreads();
        }
    }

    #pragma unroll
    for (int nd = 0; nd < 2; nd++) {
        const int col = g * 64 + wn * 16 + nd * 8 + 2 * tig;
        *(float2*)&out[(size_t)row0 * E_ + col] =
            make_float2(cacc[nd][0], cacc[nd][1]);
        *(float2*)&out[(size_t)(row0 + 8) * E_ + col] =
            make_float2(cacc[nd][2], cacc[nd][3]);
    }
}

// ---------------------------------------------------------------------------
extern "C" void kernel_launch(void* const* d_in, const int* in_sizes, int n_in,
                              void* d_out, int out_size)
{
    const float* x  = (const float*)d_in[0];
    const float* wq = (const float*)d_in[1];
    const float* bq = (const float*)d_in[2];
    const float* wk = (const float*)d_in[3];
    const float* bk = (const float*)d_in[4];
    const float* wv = (const float*)d_in[5];
    const float* bv = (const float*)d_in[6];
    const float* w1 = (const float*)d_in[7];
    const float* b1 = (const float*)d_in[8];
    const float* w2 = (const float*)d_in[9];
    const float* b2 = (const float*)d_in[10];
    const float* w3 = (const float*)d_in[11];
    const float* b3 = (const float*)d_in[12];
    const float* w4 = (const float*)d_in[13];
    const float* b4 = (const float*)d_in[14];
    float* out = (float*)d_out;

    dim3 pgrid(B_ * T_, 4);
    prep<<<pgrid, 192>>>(x, wq, wk, wv);

    dim3 ggrid(E_ / 64, (B_ * T_) / 64, 3);
    qkv_mma<<<ggrid, 256>>>(bq, bk, bv);

    dim3 kgrid(T_, B_);
    kprep<<<kgrid, 256>>>(w1);

    dim3 agrid(T_ / LT, H_, B_);
    attn_fused<<<agrid, 256>>>(b1, w2, b2, w3, b3, w4, b4, out);
}